// round 2
// baseline (speedup 1.0000x reference)
#include <cuda_runtime.h>

// ---------------------------------------------------------------------------
// 2-layer GATConv on GB300.
// Scratch in __device__ globals (no allocation). All kernels graph-capturable.
// Softmax per dst via: pass1 atomicMax (ordered-int trick), pass2 exp-sum
// (red.global.add.v4), pass3 weighted scatter (red.global.add.v4).
// NOTE: edge_index arrives as int32 (JAX x64 disabled downcasts int64->int32).
// ---------------------------------------------------------------------------

#define NN 100000

static __device__ __align__(16) float g_xl1[NN * 64];   // layer-1 transformed features
static __device__ __align__(16) float g_as1[NN * 8];    // alpha_src per head
static __device__ __align__(16) float g_ad1[NN * 8];    // alpha_dst per head
static __device__ __align__(16) int   g_amax1[NN * 8];  // ordered-int max keys
static __device__ __align__(16) float g_den1[NN * 8];   // softmax denominators
static __device__ __align__(16) float g_out1[NN * 64];  // layer-1 aggregation
static __device__ __align__(16) float g_h2[NN * 40];    // layer-2 transformed features
static __device__ __align__(16) float g_as2[NN];
static __device__ __align__(16) float g_ad2[NN];
static __device__ __align__(16) int   g_amax2[NN];
static __device__ __align__(16) float g_den2[NN];

__device__ __forceinline__ int f2o(float f) {
    int i = __float_as_int(f);
    return i >= 0 ? i : (i ^ 0x7FFFFFFF);
}
__device__ __forceinline__ float o2f(int k) {
    return __int_as_float(k >= 0 ? k : (k ^ 0x7FFFFFFF));
}
__device__ __forceinline__ float lrelu(float a) { return a > 0.f ? a : 0.2f * a; }

__device__ __forceinline__ void red4(float* p, float a, float b, float c, float d) {
    asm volatile("red.global.add.v4.f32 [%0], {%1,%2,%3,%4};"
                 :: "l"(p), "f"(a), "f"(b), "f"(c), "f"(d) : "memory");
}
__device__ __forceinline__ void red1(float* p, float a) {
    asm volatile("red.global.add.f32 [%0], %1;" :: "l"(p), "f"(a) : "memory");
}

// ---------------------------------------------------------------------------
// K1: init scratch + output (+b2 bias broadcast)
// ---------------------------------------------------------------------------
__global__ void k_init(float* __restrict__ out, const float* __restrict__ b2, int N) {
    int stride = gridDim.x * blockDim.x;
    int i0 = blockIdx.x * blockDim.x + threadIdx.x;
    for (int t = i0; t < N * 64; t += stride) g_out1[t] = 0.f;
    for (int t = i0; t < N * 8; t += stride) { g_amax1[t] = (int)0x80000000; g_den1[t] = 0.f; }
    for (int t = i0; t < N; t += stride) { g_amax2[t] = (int)0x80000000; g_den2[t] = 0.f; }
    for (int t = i0; t < N * 40; t += stride) out[t] = b2[t % 40];
}

// ---------------------------------------------------------------------------
// K2: xl1 = x @ W1  [N,64], plus per-head alpha_src/alpha_dst dot products.
// 64-row x 64-col tile, 4x4 register blocking, dynamic smem (66.5KB).
// ---------------------------------------------------------------------------
__global__ void k_gemm1(const float* __restrict__ x, const float* __restrict__ W1,
                        const float* __restrict__ a_s, const float* __restrict__ a_d, int N) {
    extern __shared__ float smem[];
    float* sW = smem;               // [128][64]
    float* sx = smem + 128 * 64;    // [64][132] padded

    const int tid = threadIdx.x;
    const int tc = tid & 15;        // 16 col groups x 4 cols
    const int tr = tid >> 4;        // 16 row groups x 4 rows

    for (int t = tid; t < 128 * 64; t += 256) sW[t] = W1[t];

    const int row0 = blockIdx.x * 64;
    for (int t = tid; t < 64 * 32; t += 256) {
        int r = t >> 5, kq = t & 31;
        int row = row0 + r;
        float4 v = (row < N) ? *(const float4*)(x + (size_t)row * 128 + kq * 4)
                             : make_float4(0.f, 0.f, 0.f, 0.f);
        float* p = sx + r * 132 + kq * 4;
        p[0] = v.x; p[1] = v.y; p[2] = v.z; p[3] = v.w;
    }
    __syncthreads();

    float acc[4][4];
#pragma unroll
    for (int i = 0; i < 4; i++)
#pragma unroll
        for (int j = 0; j < 4; j++) acc[i][j] = 0.f;

#pragma unroll 4
    for (int k = 0; k < 128; k++) {
        float4 w = *(const float4*)(sW + k * 64 + tc * 4);
#pragma unroll
        for (int i = 0; i < 4; i++) {
            float xv = sx[(tr * 4 + i) * 132 + k];
            acc[i][0] += xv * w.x; acc[i][1] += xv * w.y;
            acc[i][2] += xv * w.z; acc[i][3] += xv * w.w;
        }
    }

    float avs0 = a_s[tc * 4 + 0], avs1 = a_s[tc * 4 + 1], avs2 = a_s[tc * 4 + 2], avs3 = a_s[tc * 4 + 3];
    float avd0 = a_d[tc * 4 + 0], avd1 = a_d[tc * 4 + 1], avd2 = a_d[tc * 4 + 2], avd3 = a_d[tc * 4 + 3];

#pragma unroll
    for (int i = 0; i < 4; i++) {
        int row = row0 + tr * 4 + i;
        if (row < N) {
            *(float4*)(g_xl1 + (size_t)row * 64 + tc * 4) =
                make_float4(acc[i][0], acc[i][1], acc[i][2], acc[i][3]);
        }
        float ps = acc[i][0] * avs0 + acc[i][1] * avs1 + acc[i][2] * avs2 + acc[i][3] * avs3;
        float pd = acc[i][0] * avd0 + acc[i][1] * avd1 + acc[i][2] * avd2 + acc[i][3] * avd3;
        ps += __shfl_xor_sync(0xffffffff, ps, 1);
        pd += __shfl_xor_sync(0xffffffff, pd, 1);
        if (row < N && (tc & 1) == 0) {
            g_as1[row * 8 + (tc >> 1)] = ps;
            g_ad1[row * 8 + (tc >> 1)] = pd;
        }
    }
}

// ---------------------------------------------------------------------------
// Layer-1 edge passes. Virtual edges [E, E+N) are self loops.
// ---------------------------------------------------------------------------
__global__ void k_max1(const int* __restrict__ sp, const int* __restrict__ dp,
                       int E, int ET) {
    int t = blockIdx.x * blockDim.x + threadIdx.x;
    if (t >= ET * 8) return;
    int e = t >> 3, h = t & 7;
    int s, d;
    if (e < E) { s = sp[e]; d = dp[e]; } else { s = e - E; d = s; }
    float a = lrelu(g_as1[s * 8 + h] + g_ad1[d * 8 + h]);
    atomicMax(&g_amax1[d * 8 + h], f2o(a));
}

__global__ void k_sum1(const int* __restrict__ sp, const int* __restrict__ dp,
                       int E, int ET) {
    int t = blockIdx.x * blockDim.x + threadIdx.x;
    if (t >= ET * 2) return;
    int e = t >> 1, j = (t & 1) * 4;
    int s, d;
    if (e < E) { s = sp[e]; d = dp[e]; } else { s = e - E; d = s; }
    float4 as = *(const float4*)(g_as1 + s * 8 + j);
    float4 ad = *(const float4*)(g_ad1 + d * 8 + j);
    int4 mk = *(const int4*)(g_amax1 + d * 8 + j);
    float e0 = expf(lrelu(as.x + ad.x) - o2f(mk.x));
    float e1 = expf(lrelu(as.y + ad.y) - o2f(mk.y));
    float e2 = expf(lrelu(as.z + ad.z) - o2f(mk.z));
    float e3 = expf(lrelu(as.w + ad.w) - o2f(mk.w));
    red4(g_den1 + d * 8 + j, e0, e1, e2, e3);
}

__global__ void k_sc1(const int* __restrict__ sp, const int* __restrict__ dp,
                      int E, int ET) {
    int t = blockIdx.x * blockDim.x + threadIdx.x;
    if (t >= ET * 16) return;
    int e = t >> 4, j = t & 15;      // j: 4-col group, head = j>>1
    int h = j >> 1;
    int s, d;
    if (e < E) { s = sp[e]; d = dp[e]; } else { s = e - E; d = s; }
    float a = lrelu(g_as1[s * 8 + h] + g_ad1[d * 8 + h]);
    float attn = expf(a - o2f(g_amax1[d * 8 + h])) / (g_den1[d * 8 + h] + 1e-16f);
    float4 v = *(const float4*)(g_xl1 + (size_t)s * 64 + j * 4);
    red4(g_out1 + (size_t)d * 64 + j * 4, v.x * attn, v.y * attn, v.z * attn, v.w * attn);
}

// ---------------------------------------------------------------------------
// K6: h2 = elu(out1 + b1) @ W2   [N,40].  64-row tile, 4x4 blocking (tc=10).
// ---------------------------------------------------------------------------
__global__ void k_gemm2(const float* __restrict__ W2, const float* __restrict__ b1v, int N) {
    __shared__ float sW[64 * 40];
    __shared__ float sx[64 * 66];
    const int tid = threadIdx.x;

    for (int t = tid; t < 64 * 40; t += 160) sW[t] = W2[t];

    const int row0 = blockIdx.x * 64;
    for (int t = tid; t < 64 * 16; t += 160) {
        int r = t >> 4, kq = t & 15;
        int row = row0 + r;
        float4 v = (row < N) ? *(const float4*)(g_out1 + (size_t)row * 64 + kq * 4)
                             : make_float4(0.f, 0.f, 0.f, 0.f);
        v.x += b1v[kq * 4 + 0]; v.y += b1v[kq * 4 + 1];
        v.z += b1v[kq * 4 + 2]; v.w += b1v[kq * 4 + 3];
        v.x = v.x > 0.f ? v.x : expm1f(v.x);
        v.y = v.y > 0.f ? v.y : expm1f(v.y);
        v.z = v.z > 0.f ? v.z : expm1f(v.z);
        v.w = v.w > 0.f ? v.w : expm1f(v.w);
        float* p = sx + r * 66 + kq * 4;
        p[0] = v.x; p[1] = v.y; p[2] = v.z; p[3] = v.w;
    }
    __syncthreads();

    const int tc = tid % 10, tr = tid / 10;   // 10 col groups x 4, 16 row groups x 4
    float acc[4][4];
#pragma unroll
    for (int i = 0; i < 4; i++)
#pragma unroll
        for (int j = 0; j < 4; j++) acc[i][j] = 0.f;

#pragma unroll 4
    for (int k = 0; k < 64; k++) {
        float4 w = *(const float4*)(sW + k * 40 + tc * 4);
#pragma unroll
        for (int i = 0; i < 4; i++) {
            float xv = sx[(tr * 4 + i) * 66 + k];
            acc[i][0] += xv * w.x; acc[i][1] += xv * w.y;
            acc[i][2] += xv * w.z; acc[i][3] += xv * w.w;
        }
    }
#pragma unroll
    for (int i = 0; i < 4; i++) {
        int row = row0 + tr * 4 + i;
        if (row < N)
            *(float4*)(g_h2 + (size_t)row * 40 + tc * 4) =
                make_float4(acc[i][0], acc[i][1], acc[i][2], acc[i][3]);
    }
}

// K6b: layer-2 attention logits per node.
__global__ void k_alpha2(const float* __restrict__ asv, const float* __restrict__ adv, int N) {
    int n = blockIdx.x * blockDim.x + threadIdx.x;
    if (n >= N) return;
    const float* h = g_h2 + (size_t)n * 40;
    float ss = 0.f, sd = 0.f;
#pragma unroll
    for (int c = 0; c < 40; c += 4) {
        float4 v = *(const float4*)(h + c);
        ss += v.x * asv[c] + v.y * asv[c + 1] + v.z * asv[c + 2] + v.w * asv[c + 3];
        sd += v.x * adv[c] + v.y * adv[c + 1] + v.z * adv[c + 2] + v.w * adv[c + 3];
    }
    g_as2[n] = ss;
    g_ad2[n] = sd;
}

// ---------------------------------------------------------------------------
// Layer-2 edge passes (single head, 40 channels).
// ---------------------------------------------------------------------------
__global__ void k_max2(const int* __restrict__ sp, const int* __restrict__ dp,
                       int E, int ET) {
    int e = blockIdx.x * blockDim.x + threadIdx.x;
    if (e >= ET) return;
    int s, d;
    if (e < E) { s = sp[e]; d = dp[e]; } else { s = e - E; d = s; }
    float a = lrelu(g_as2[s] + g_ad2[d]);
    atomicMax(&g_amax2[d], f2o(a));
}

__global__ void k_sum2(const int* __restrict__ sp, const int* __restrict__ dp,
                       int E, int ET) {
    int e = blockIdx.x * blockDim.x + threadIdx.x;
    if (e >= ET) return;
    int s, d;
    if (e < E) { s = sp[e]; d = dp[e]; } else { s = e - E; d = s; }
    float a = lrelu(g_as2[s] + g_ad2[d]);
    red1(g_den2 + d, expf(a - o2f(g_amax2[d])));
}

__global__ void k_sc2(const int* __restrict__ sp, const int* __restrict__ dp,
                      int E, int ET, float* __restrict__ out) {
    int t = blockIdx.x * blockDim.x + threadIdx.x;
    if (t >= ET * 10) return;
    unsigned int e = (unsigned int)t / 10u;
    int j = t - (int)e * 10;
    int s, d;
    if ((int)e < E) { s = sp[e]; d = dp[e]; } else { s = (int)e - E; d = s; }
    float a = lrelu(g_as2[s] + g_ad2[d]);
    float attn = expf(a - o2f(g_amax2[d])) / (g_den2[d] + 1e-16f);
    float4 v = *(const float4*)(g_h2 + (size_t)s * 40 + j * 4);
    red4(out + (size_t)d * 40 + j * 4, v.x * attn, v.y * attn, v.z * attn, v.w * attn);
}

// ---------------------------------------------------------------------------
extern "C" void kernel_launch(void* const* d_in, const int* in_sizes, int n_in,
                              void* d_out, int out_size) {
    const float* x = (const float*)d_in[0];
    const int* ei = (const int*)d_in[1];   // int32: JAX x64-disabled downcast
    const float* W1 = (const float*)d_in[2];
    const float* a_src1 = (const float*)d_in[3];
    const float* a_dst1 = (const float*)d_in[4];
    const float* b1 = (const float*)d_in[5];
    const float* W2 = (const float*)d_in[6];
    const float* a_src2 = (const float*)d_in[7];
    const float* a_dst2 = (const float*)d_in[8];
    const float* b2 = (const float*)d_in[9];
    float* out = (float*)d_out;

    const int N = in_sizes[0] / 128;
    const int E = in_sizes[1] / 2;
    const int ET = E + N;  // real edges + self loops
    const int* src = ei;
    const int* dst = ei + E;

    static const int GEMM1_SMEM = (128 * 64 + 64 * 132) * (int)sizeof(float);
    cudaFuncSetAttribute(k_gemm1, cudaFuncAttributeMaxDynamicSharedMemorySize, GEMM1_SMEM);

    k_init<<<4096, 256>>>(out, b2, N);
    k_gemm1<<<(N + 63) / 64, 256, GEMM1_SMEM>>>(x, W1, a_src1, a_dst1, N);
    k_max1<<<(ET * 8 + 255) / 256, 256>>>(src, dst, E, ET);
    k_sum1<<<(ET * 2 + 255) / 256, 256>>>(src, dst, E, ET);
    k_sc1<<<(ET * 16 + 255) / 256, 256>>>(src, dst, E, ET);
    k_gemm2<<<(N + 63) / 64, 160>>>(W2, b1, N);
    k_alpha2<<<(N + 255) / 256, 256>>>(a_src2, a_dst2, N);
    k_max2<<<(ET + 255) / 256, 256>>>(src, dst, E, ET);
    k_sum2<<<(ET + 255) / 256, 256>>>(src, dst, E, ET);
    k_sc2<<<(ET * 10 + 255) / 256, 256>>>(src, dst, E, ET, out);
}

// round 3
// speedup vs baseline: 1.3580x; 1.3580x over previous
#include <cuda_runtime.h>

// ---------------------------------------------------------------------------
// 2-layer GATConv on GB300 — round 3.
// Softmax restructured: no max pass (fp32-safe logit range), and the exp-sum
// is fused into the weighted scatter (normalize per-node afterwards, folded
// into the next GEMM's load / a tiny output pass). One edge pass per layer.
// ---------------------------------------------------------------------------

#define NN 100000

static __device__ __align__(16) float g_xl1[NN * 64];   // layer-1 transformed features
static __device__ __align__(16) float g_as1[NN * 8];    // alpha_src per head
static __device__ __align__(16) float g_ad1[NN * 8];    // alpha_dst per head
static __device__ __align__(16) float g_den1[NN * 8];   // softmax denominators
static __device__ __align__(16) float g_out1[NN * 64];  // layer-1 aggregation (unnormalized)
static __device__ __align__(16) float g_h2[NN * 40];    // layer-2 transformed features
static __device__ __align__(16) float g_as2[NN];
static __device__ __align__(16) float g_ad2[NN];
static __device__ __align__(16) float g_den2[NN];

__device__ __forceinline__ float lrelu(float a) { return a > 0.f ? a : 0.2f * a; }

__device__ __forceinline__ void red4(float* p, float a, float b, float c, float d) {
    asm volatile("red.global.add.v4.f32 [%0], {%1,%2,%3,%4};"
                 :: "l"(p), "f"(a), "f"(b), "f"(c), "f"(d) : "memory");
}
__device__ __forceinline__ void red1(float* p, float a) {
    asm volatile("red.global.add.f32 [%0], %1;" :: "l"(p), "f"(a) : "memory");
}

// ---------------------------------------------------------------------------
// K1: zero scratch accumulators + output
// ---------------------------------------------------------------------------
__global__ void k_init(float* __restrict__ out, int N) {
    int stride = gridDim.x * blockDim.x;
    int i0 = blockIdx.x * blockDim.x + threadIdx.x;
    for (int t = i0; t < N * 64; t += stride) g_out1[t] = 0.f;
    for (int t = i0; t < N * 8; t += stride) g_den1[t] = 0.f;
    for (int t = i0; t < N; t += stride) g_den2[t] = 0.f;
    for (int t = i0; t < N * 40; t += stride) out[t] = 0.f;
}

// ---------------------------------------------------------------------------
// K2: xl1 = x @ W1  [N,64], plus per-head alpha_src/alpha_dst dot products.
// ---------------------------------------------------------------------------
__global__ void k_gemm1(const float* __restrict__ x, const float* __restrict__ W1,
                        const float* __restrict__ a_s, const float* __restrict__ a_d, int N) {
    extern __shared__ float smem[];
    float* sW = smem;               // [128][64]
    float* sx = smem + 128 * 64;    // [64][132] padded

    const int tid = threadIdx.x;
    const int tc = tid & 15;
    const int tr = tid >> 4;

    for (int t = tid; t < 128 * 64; t += 256) sW[t] = W1[t];

    const int row0 = blockIdx.x * 64;
    for (int t = tid; t < 64 * 32; t += 256) {
        int r = t >> 5, kq = t & 31;
        int row = row0 + r;
        float4 v = (row < N) ? *(const float4*)(x + (size_t)row * 128 + kq * 4)
                             : make_float4(0.f, 0.f, 0.f, 0.f);
        float* p = sx + r * 132 + kq * 4;
        p[0] = v.x; p[1] = v.y; p[2] = v.z; p[3] = v.w;
    }
    __syncthreads();

    float acc[4][4];
#pragma unroll
    for (int i = 0; i < 4; i++)
#pragma unroll
        for (int j = 0; j < 4; j++) acc[i][j] = 0.f;

#pragma unroll 4
    for (int k = 0; k < 128; k++) {
        float4 w = *(const float4*)(sW + k * 64 + tc * 4);
#pragma unroll
        for (int i = 0; i < 4; i++) {
            float xv = sx[(tr * 4 + i) * 132 + k];
            acc[i][0] += xv * w.x; acc[i][1] += xv * w.y;
            acc[i][2] += xv * w.z; acc[i][3] += xv * w.w;
        }
    }

    float avs0 = a_s[tc * 4 + 0], avs1 = a_s[tc * 4 + 1], avs2 = a_s[tc * 4 + 2], avs3 = a_s[tc * 4 + 3];
    float avd0 = a_d[tc * 4 + 0], avd1 = a_d[tc * 4 + 1], avd2 = a_d[tc * 4 + 2], avd3 = a_d[tc * 4 + 3];

#pragma unroll
    for (int i = 0; i < 4; i++) {
        int row = row0 + tr * 4 + i;
        if (row < N) {
            *(float4*)(g_xl1 + (size_t)row * 64 + tc * 4) =
                make_float4(acc[i][0], acc[i][1], acc[i][2], acc[i][3]);
        }
        float ps = acc[i][0] * avs0 + acc[i][1] * avs1 + acc[i][2] * avs2 + acc[i][3] * avs3;
        float pd = acc[i][0] * avd0 + acc[i][1] * avd1 + acc[i][2] * avd2 + acc[i][3] * avd3;
        ps += __shfl_xor_sync(0xffffffff, ps, 1);
        pd += __shfl_xor_sync(0xffffffff, pd, 1);
        if (row < N && (tc & 1) == 0) {
            g_as1[row * 8 + (tc >> 1)] = ps;
            g_ad1[row * 8 + (tc >> 1)] = pd;
        }
    }
}

// ---------------------------------------------------------------------------
// K3: layer-1 fused edge pass. ea = exp(lrelu(alpha)); scatter ea*xl and ea.
// t = e*16 + j ; j = 4-col group (head = j>>1). Virtual edges = self loops.
// ---------------------------------------------------------------------------
__global__ void k_fused1(const int* __restrict__ sp, const int* __restrict__ dp,
                         int E, int ET) {
    int t = blockIdx.x * blockDim.x + threadIdx.x;
    if (t >= ET * 16) return;
    int e = t >> 4, j = t & 15;
    int h = j >> 1;
    int s, d;
    if (e < E) { s = sp[e]; d = dp[e]; } else { s = e - E; d = s; }
    float ea = __expf(lrelu(g_as1[s * 8 + h] + g_ad1[d * 8 + h]));
    float4 v = *(const float4*)(g_xl1 + (size_t)s * 64 + j * 4);
    red4(g_out1 + (size_t)d * 64 + j * 4, v.x * ea, v.y * ea, v.z * ea, v.w * ea);
    if ((j & 1) == 0) red1(g_den1 + d * 8 + h, ea);
}

// ---------------------------------------------------------------------------
// K4: h2 = elu(out1/den1 + b1) @ W2   [N,40]. Normalization folded into load.
// ---------------------------------------------------------------------------
__global__ void k_gemm2(const float* __restrict__ W2, const float* __restrict__ b1v, int N) {
    __shared__ float sW[64 * 40];
    __shared__ float sx[64 * 66];
    const int tid = threadIdx.x;

    for (int t = tid; t < 64 * 40; t += 160) sW[t] = W2[t];

    const int row0 = blockIdx.x * 64;
    for (int t = tid; t < 64 * 16; t += 160) {
        int r = t >> 4, kq = t & 15;
        int row = row0 + r;
        float4 v = make_float4(0.f, 0.f, 0.f, 0.f);
        if (row < N) {
            v = *(const float4*)(g_out1 + (size_t)row * 64 + kq * 4);
            float inv = 1.f / (g_den1[row * 8 + (kq >> 1)] + 1e-16f);
            v.x *= inv; v.y *= inv; v.z *= inv; v.w *= inv;
        }
        v.x += b1v[kq * 4 + 0]; v.y += b1v[kq * 4 + 1];
        v.z += b1v[kq * 4 + 2]; v.w += b1v[kq * 4 + 3];
        v.x = v.x > 0.f ? v.x : expm1f(v.x);
        v.y = v.y > 0.f ? v.y : expm1f(v.y);
        v.z = v.z > 0.f ? v.z : expm1f(v.z);
        v.w = v.w > 0.f ? v.w : expm1f(v.w);
        float* p = sx + r * 66 + kq * 4;
        p[0] = v.x; p[1] = v.y; p[2] = v.z; p[3] = v.w;
    }
    __syncthreads();

    const int tc = tid % 10, tr = tid / 10;
    float acc[4][4];
#pragma unroll
    for (int i = 0; i < 4; i++)
#pragma unroll
        for (int j = 0; j < 4; j++) acc[i][j] = 0.f;

#pragma unroll 4
    for (int k = 0; k < 64; k++) {
        float4 w = *(const float4*)(sW + k * 40 + tc * 4);
#pragma unroll
        for (int i = 0; i < 4; i++) {
            float xv = sx[(tr * 4 + i) * 66 + k];
            acc[i][0] += xv * w.x; acc[i][1] += xv * w.y;
            acc[i][2] += xv * w.z; acc[i][3] += xv * w.w;
        }
    }
#pragma unroll
    for (int i = 0; i < 4; i++) {
        int row = row0 + tr * 4 + i;
        if (row < N)
            *(float4*)(g_h2 + (size_t)row * 40 + tc * 4) =
                make_float4(acc[i][0], acc[i][1], acc[i][2], acc[i][3]);
    }
}

// K5: layer-2 attention logits per node.
__global__ void k_alpha2(const float* __restrict__ asv, const float* __restrict__ adv, int N) {
    int n = blockIdx.x * blockDim.x + threadIdx.x;
    if (n >= N) return;
    const float* h = g_h2 + (size_t)n * 40;
    float ss = 0.f, sd = 0.f;
#pragma unroll
    for (int c = 0; c < 40; c += 4) {
        float4 v = *(const float4*)(h + c);
        ss += v.x * asv[c] + v.y * asv[c + 1] + v.z * asv[c + 2] + v.w * asv[c + 3];
        sd += v.x * adv[c] + v.y * adv[c + 1] + v.z * adv[c + 2] + v.w * adv[c + 3];
    }
    g_as2[n] = ss;
    g_ad2[n] = sd;
}

// ---------------------------------------------------------------------------
// K6: layer-2 fused edge pass. Scatter ea*h2 into out (unnormalized) and ea.
// ---------------------------------------------------------------------------
__global__ void k_fused2(const int* __restrict__ sp, const int* __restrict__ dp,
                         int E, int ET, float* __restrict__ out) {
    int t = blockIdx.x * blockDim.x + threadIdx.x;
    if (t >= ET * 10) return;
    unsigned int e = (unsigned int)t / 10u;
    int j = t - (int)e * 10;
    int s, d;
    if ((int)e < E) { s = sp[e]; d = dp[e]; } else { s = (int)e - E; d = s; }
    float ea = __expf(lrelu(g_as2[s] + g_ad2[d]));
    float4 v = *(const float4*)(g_h2 + (size_t)s * 40 + j * 4);
    red4(out + (size_t)d * 40 + j * 4, v.x * ea, v.y * ea, v.z * ea, v.w * ea);
    if (j == 0) red1(g_den2 + d, ea);
}

// K7: normalize output in place, add b2.
__global__ void k_out(float* __restrict__ out, const float* __restrict__ b2, int N) {
    int t = blockIdx.x * blockDim.x + threadIdx.x;
    if (t >= N * 10) return;
    int n = (unsigned int)t / 10u;
    int j = t - n * 10;
    float inv = 1.f / (g_den2[n] + 1e-16f);
    float4 v = *(const float4*)(out + (size_t)n * 40 + j * 4);
    v.x = v.x * inv + b2[j * 4 + 0];
    v.y = v.y * inv + b2[j * 4 + 1];
    v.z = v.z * inv + b2[j * 4 + 2];
    v.w = v.w * inv + b2[j * 4 + 3];
    *(float4*)(out + (size_t)n * 40 + j * 4) = v;
}

// ---------------------------------------------------------------------------
extern "C" void kernel_launch(void* const* d_in, const int* in_sizes, int n_in,
                              void* d_out, int out_size) {
    const float* x = (const float*)d_in[0];
    const int* ei = (const int*)d_in[1];   // int32 (JAX x64-disabled downcast)
    const float* W1 = (const float*)d_in[2];
    const float* a_src1 = (const float*)d_in[3];
    const float* a_dst1 = (const float*)d_in[4];
    const float* b1 = (const float*)d_in[5];
    const float* W2 = (const float*)d_in[6];
    const float* a_src2 = (const float*)d_in[7];
    const float* a_dst2 = (const float*)d_in[8];
    const float* b2 = (const float*)d_in[9];
    float* out = (float*)d_out;

    const int N = in_sizes[0] / 128;
    const int E = in_sizes[1] / 2;
    const int ET = E + N;
    const int* src = ei;
    const int* dst = ei + E;

    static const int GEMM1_SMEM = (128 * 64 + 64 * 132) * (int)sizeof(float);
    cudaFuncSetAttribute(k_gemm1, cudaFuncAttributeMaxDynamicSharedMemorySize, GEMM1_SMEM);

    k_init<<<4096, 256>>>(out, N);
    k_gemm1<<<(N + 63) / 64, 256, GEMM1_SMEM>>>(x, W1, a_src1, a_dst1, N);
    k_fused1<<<(ET * 16 + 255) / 256, 256>>>(src, dst, E, ET);
    k_gemm2<<<(N + 63) / 64, 160>>>(W2, b1, N);
    k_alpha2<<<(N + 255) / 256, 256>>>(a_src2, a_dst2, N);
    k_fused2<<<(ET * 10 + 255) / 256, 256>>>(src, dst, E, ET, out);
    k_out<<<(N * 10 + 255) / 256, 256>>>(out, b2, N);
}